// round 1
// baseline (speedup 1.0000x reference)
#include <cuda_runtime.h>
#include <cstddef>

#define NN 2048
#define EE 32
#define R2F 0.0025f   // float32(0.05^2), matches JAX's weak-typed scalar promotion

// Rare path: 2-layer MLP for one valid edge, this lane produces output
// features [4*eb, 4*eb+4). Weights pre-staged in shared memory as float4.
// __noinline__ keeps the hot store loop small (I$) — called for ~3% of
// store iterations only.
__device__ __noinline__ float4 edge_mlp(float rx, float ry,
                                        const float4* __restrict__ sW1p,
                                        const float4* __restrict__ sW2,
                                        const float4* __restrict__ sb2,
                                        int eb) {
    float4 acc = sb2[eb];
#pragma unroll 8
    for (int j = 0; j < 32; j++) {
        float4 w1 = sW1p[j];                         // {W1[0][j], W1[1][j], b1[j], 0}
        float h = fmaf(ry, w1.y, fmaf(rx, w1.x, w1.z));
        h = fmaxf(h, 0.0f);
        float4 w2 = sW2[j * 8 + eb];                 // W2[j][4eb .. 4eb+3]
        acc.x = fmaf(h, w2.x, acc.x);
        acc.y = fmaf(h, w2.y, acc.y);
        acc.z = fmaf(h, w2.z, acc.z);
        acc.w = fmaf(h, w2.w, acc.w);
    }
    return acc;
}

// One block per source node s (grid = 2048, block = 256 = 8 warps).
// Each warp handles d-chunks of 32 destinations: chunk c = warp, warp+8, ...
// Per chunk: lane loads pos[d0+lane] (coalesced float2), then 8 store
// iterations; iteration i covers pairs d0+4i..d0+4i+3, lane writes float4
// (features 4*(lane&7)..) of pair d0+4i+(lane>>3). Warp store = 512B contiguous.
__global__ void __launch_bounds__(256)
graph_edges_kernel(const float* __restrict__ pos,
                   const float* __restrict__ W1,
                   const float* __restrict__ b1,
                   const float* __restrict__ W2,
                   const float* __restrict__ b2,
                   float4* __restrict__ out) {
    __shared__ float4 sW1p[32];    // packed {W1x, W1y, b1, 0}
    __shared__ float4 sW2[256];    // W2[32][32] as 32 rows x 8 float4
    __shared__ float4 sb2[8];

    const int tid = threadIdx.x;
    if (tid < 32) sW1p[tid] = make_float4(W1[tid], W1[32 + tid], b1[tid], 0.0f);
    sW2[tid] = ((const float4*)W2)[tid];             // 256 float4 = 1024 floats
    if (tid < 8) sb2[tid] = ((const float4*)b2)[tid];
    __syncthreads();

    const int lane = tid & 31;
    const int warp = tid >> 5;
    const int grp  = lane >> 3;    // which of 4 pairs in a store iteration
    const int eb   = lane & 7;     // which float4 of the 32 features
    const int s    = blockIdx.x;

    const float2 ps = ((const float2*)pos)[s];

    for (int c = warp; c < NN / 32; c += 8) {
        const int d0 = c * 32;
        const float2 pd = ((const float2*)pos)[d0 + lane];
        const float rx = pd.x - ps.x;    // pos[dst] - pos[src], matches reference
        const float ry = pd.y - ps.y;

        const size_t base = ((size_t)s * NN + (size_t)d0) * (EE / 4);

#pragma unroll 1
        for (int i = 0; i < 8; i++) {
            const int src = i * 4 + grp;                 // lane that owns my pair's rel_pos
            const float frx = __shfl_sync(0xffffffffu, rx, src);
            const float fry = __shfl_sync(0xffffffffu, ry, src);
            // no-FMA dist2: bit-exact with jnp (mul, mul, add in f32)
            const float d2 = __fadd_rn(__fmul_rn(frx, frx), __fmul_rn(fry, fry));
            const bool valid = (d2 <= R2F) && ((d0 + src) != s);

            float4 v = make_float4(0.0f, 0.0f, 0.0f, 0.0f);
            if (valid) v = edge_mlp(frx, fry, sW1p, sW2, sb2, eb);

            out[base + (size_t)i * 32 + lane] = v;       // 512B/warp, fully coalesced
        }
    }
}

// Inputs (metadata order): node_features (unused), object_positions_2d,
// W1, b1, W2, b2. Output: edge_attr [N, N, E] fp32.
extern "C" void kernel_launch(void* const* d_in, const int* in_sizes, int n_in,
                              void* d_out, int out_size) {
    const float* pos = (const float*)d_in[1];
    const float* W1  = (const float*)d_in[2];
    const float* b1  = (const float*)d_in[3];
    const float* W2  = (const float*)d_in[4];
    const float* b2  = (const float*)d_in[5];
    graph_edges_kernel<<<NN, 256>>>(pos, W1, b1, W2, b2, (float4*)d_out);
}